// round 1
// baseline (speedup 1.0000x reference)
#include <cuda_runtime.h>
#include <math.h>

// Problem constants
#define T_     128
#define NSEQ   256          // B*S = 32*8
#define EMBED  512
#define UNITS  512
#define G4     2048         // 4*UNITS
#define NZ     4096         // both directions

// ---------------- scratch (device globals: no allocation allowed) ----------
__device__ float g_xW[(size_t)NSEQ * T_ * NZ];   // [s*T+t][4096] : fwd cols 0..2047, bwd cols 2048..4095 (bias included)
__device__ float g_h[2][2][NSEQ * UNITS];        // [parity][dir][s*512+u]
__device__ float g_c[2][NSEQ * UNITS];           // [dir][s*512+u]

__device__ __forceinline__ float sigm(float x) { return 1.f / (1.f + expf(-x)); }

// ---------------- zero initial state (deterministic across replays) --------
__global__ __launch_bounds__(256) void zero_state() {
    int i = blockIdx.x * 256 + threadIdx.x;
    if (i < NSEQ * UNITS) {
        g_h[0][0][i] = 0.f;
        g_h[0][1][i] = 0.f;
        g_c[0][i]    = 0.f;
        g_c[1][i]    = 0.f;
    }
}

// ---------------- Phase 1: fused embedding gather + GEMM -------------------
// xW[r][c] = sum_k emb_table[ids[r]][k] * W[k][c] + b[c]
// M = 32768 (r = s*T+t), K = 512, N = 4096 (cols < 2048: W_f/b_f, else W_b/b_b)
// Tile 128x128, K-chunk 16, 256 threads, 8x8 per thread.
__global__ __launch_bounds__(256) void embed_gemm(
    const int* __restrict__ x, const float* __restrict__ emb,
    const float* __restrict__ W_f, const float* __restrict__ b_f,
    const float* __restrict__ W_b, const float* __restrict__ b_b)
{
    __shared__ float As[128][20];   // [m][k], padded (80B rows, 16B aligned)
    __shared__ float Bs[16][132];   // [k][c], padded (528B rows, 16B aligned)
    __shared__ int   ids_s[128];

    const int tid = threadIdx.x;
    const int tx = tid & 15;        // col octet 0..15
    const int ty = tid >> 4;        // row octet 0..15
    const int mBase = blockIdx.y * 128;
    const int nBase = blockIdx.x * 128;

    const float* W  = (nBase < G4) ? W_f : W_b;
    const float* bp = (nBase < G4) ? b_f : b_b;
    const int nOff  = (nBase < G4) ? nBase : (nBase - G4);

    if (tid < 128) ids_s[tid] = x[mBase + tid];
    __syncthreads();

    float acc[8][8] = {};

    for (int k0 = 0; k0 < EMBED; k0 += 16) {
        // A tile: 128 rows x 16 k (gathered embedding rows)
        {
            int lm = tid >> 1;
            int kh = (tid & 1) * 8;
            const float* src = emb + (size_t)ids_s[lm] * EMBED + k0 + kh;
            float4 v0 = *(const float4*)(src);
            float4 v1 = *(const float4*)(src + 4);
            *(float4*)&As[lm][kh]     = v0;
            *(float4*)&As[lm][kh + 4] = v1;
        }
        // B tile: 16 k x 128 cols
        {
            int kb = tid >> 4;
            int cb = (tid & 15) * 8;
            const float* src = W + (size_t)(k0 + kb) * G4 + nOff + cb;
            *(float4*)&Bs[kb][cb]     = *(const float4*)(src);
            *(float4*)&Bs[kb][cb + 4] = *(const float4*)(src + 4);
        }
        __syncthreads();

        #pragma unroll
        for (int k = 0; k < 16; k++) {
            float a[8], b[8];
            #pragma unroll
            for (int i = 0; i < 8; i++) a[i] = As[ty * 8 + i][k];
            float4 b0 = *(float4*)&Bs[k][tx * 8];
            float4 b1 = *(float4*)&Bs[k][tx * 8 + 4];
            b[0]=b0.x; b[1]=b0.y; b[2]=b0.z; b[3]=b0.w;
            b[4]=b1.x; b[5]=b1.y; b[6]=b1.z; b[7]=b1.w;
            #pragma unroll
            for (int i = 0; i < 8; i++)
                #pragma unroll
                for (int j = 0; j < 8; j++)
                    acc[i][j] = fmaf(a[i], b[j], acc[i][j]);
        }
        __syncthreads();
    }

    // epilogue: add bias, store fp32
    #pragma unroll
    for (int i = 0; i < 8; i++) {
        size_t row = (size_t)(mBase + ty * 8 + i);
        float* dst = g_xW + row * NZ + nBase + tx * 8;
        const float* bsrc = bp + nOff + tx * 8;
        #pragma unroll
        for (int j = 0; j < 8; j++) dst[j] = acc[i][j] + bsrc[j];
    }
}

// ---------------- Phase 2: one recurrent step (launched 128x) --------------
// grid (32 colblks, 2 rowblks, 2 dirs). Each CTA: rows = 128 seqs, 16 h-cols
// => 64 z-cols (4 gates x 16). z = xW[t] + h_prev @ U_slice; gate update with
// Keras masking (hold state where token id == 0). h double-buffered in global;
// c owned exclusively by this CTA's threads.
__global__ __launch_bounds__(256) void lstm_step(
    const int* __restrict__ x,
    const float* __restrict__ U_f, const float* __restrict__ U_b,
    int sIdx)
{
    const int cb  = blockIdx.x;       // 0..31  (16 h-cols each)
    const int rb  = blockIdx.y;       // 0..1   (128 rows each)
    const int dir = blockIdx.z;       // 0 fwd, 1 bwd
    const int parity = sIdx & 1;
    const float* U = dir ? U_b : U_f;
    const int t = dir ? (T_ - 1 - sIdx) : sIdx;
    const int rBase = rb * 128;

    __shared__ float Hs[128][36];     // [r][k], padded
    __shared__ float Us[32][64];      // [k][g*16 + hl]

    const int tid = threadIdx.x;
    const int tx = tid & 7;           // 2 h-cols each -> 16 h-cols
    const int ty = tid >> 3;          // 0..31, 4 rows each -> 128 rows

    const float* hin = g_h[parity][dir];
    float acc[4][8] = {};             // [row i][hh*4 + gate]

    for (int k0 = 0; k0 < UNITS; k0 += 32) {
        // H tile: 128 rows x 32 k
        #pragma unroll
        for (int p = 0; p < 4; p++) {
            int q  = p * 256 + tid;            // 0..1023
            int r  = q >> 3;
            int kv = (q & 7) * 4;
            float4 v = *(const float4*)&hin[(rBase + r) * UNITS + k0 + kv];
            *(float4*)&Hs[r][kv] = v;
        }
        // U tile: 32 k x 64 cols, layout col = g*16 + hl, global col = g*512 + cb*16 + hl
        {
            int kU  = tid >> 3;
            int lc  = (tid & 7) * 8;
            int g   = lc >> 4;                 // constant across the 8 elems
            int hl0 = lc & 15;
            const float* src = U + (size_t)(k0 + kU) * G4 + g * 512 + cb * 16 + hl0;
            *(float4*)&Us[kU][lc]     = *(const float4*)(src);
            *(float4*)&Us[kU][lc + 4] = *(const float4*)(src + 4);
        }
        __syncthreads();

        #pragma unroll
        for (int k = 0; k < 32; k++) {
            float a[4];
            #pragma unroll
            for (int i = 0; i < 4; i++) a[i] = Hs[ty * 4 + i][k];
            #pragma unroll
            for (int g = 0; g < 4; g++) {
                float2 b2 = *(float2*)&Us[k][g * 16 + tx * 2];
                #pragma unroll
                for (int i = 0; i < 4; i++) {
                    acc[i][0 * 4 + g] = fmaf(a[i], b2.x, acc[i][0 * 4 + g]);
                    acc[i][1 * 4 + g] = fmaf(a[i], b2.y, acc[i][1 * 4 + g]);
                }
            }
        }
        __syncthreads();
    }

    // gate epilogue
    float* hout = g_h[parity ^ 1][dir];
    float* c    = g_c[dir];
    #pragma unroll
    for (int i = 0; i < 4; i++) {
        int s = rBase + ty * 4 + i;
        bool m = (x[s * T_ + t] != 0);
        const float* xw = g_xW + ((size_t)s * T_ + t) * NZ + dir * G4;
        #pragma unroll
        for (int hh = 0; hh < 2; hh++) {
            int hcol = cb * 16 + tx * 2 + hh;
            float zi = acc[i][hh * 4 + 0] + xw[hcol];
            float zf = acc[i][hh * 4 + 1] + xw[512 + hcol];
            float zg = acc[i][hh * 4 + 2] + xw[1024 + hcol];
            float zo = acc[i][hh * 4 + 3] + xw[1536 + hcol];
            float ig = sigm(zi), fg = sigm(zf);
            float gg = tanhf(zg), og = sigm(zo);
            int idx = s * UNITS + hcol;
            float cold = c[idx];
            float cnew = fg * cold + ig * gg;
            float hnew = og * tanhf(cnew);
            if (m) c[idx] = cnew;
            hout[idx] = m ? hnew : hin[idx];
        }
    }
}

// ---------------- output: concat [h_fwd | h_bwd] ---------------------------
__global__ __launch_bounds__(256) void write_out(float* __restrict__ out) {
    int i = blockIdx.x * 256 + threadIdx.x;   // 0 .. 262143
    int s = i >> 10;
    int u = i & 1023;
    float v = (u < 512) ? g_h[0][0][s * 512 + u]
                        : g_h[0][1][s * 512 + (u - 512)];
    out[i] = v;
}

// ---------------- launcher -------------------------------------------------
extern "C" void kernel_launch(void* const* d_in, const int* in_sizes, int n_in,
                              void* d_out, int out_size)
{
    const int*   x   = (const int*)  d_in[0];
    const float* emb = (const float*)d_in[1];
    const float* W_f = (const float*)d_in[2];
    const float* U_f = (const float*)d_in[3];
    const float* b_f = (const float*)d_in[4];
    const float* W_b = (const float*)d_in[5];
    const float* U_b = (const float*)d_in[6];
    const float* b_b = (const float*)d_in[7];
    float* out = (float*)d_out;

    zero_state<<<(NSEQ * UNITS + 255) / 256, 256>>>();
    embed_gemm<<<dim3(NZ / 128, (NSEQ * T_) / 128), 256>>>(x, emb, W_f, b_f, W_b, b_b);
    for (int s = 0; s < T_; s++)
        lstm_step<<<dim3(32, 2, 2), 256>>>(x, U_f, U_b, s);
    write_out<<<(NSEQ * 1024) / 256, 256>>>(out);
}

// round 2
// speedup vs baseline: 1.4593x; 1.4593x over previous
#include <cuda_runtime.h>
#include <math.h>
#include <stdint.h>

// Problem constants
#define T_     128
#define NSEQ   256          // B*S = 32*8
#define EMBED  512
#define UNITS  512
#define G4     2048         // 4*UNITS
#define NZ     4096         // both directions

// ---------------- scratch (device globals: no allocation allowed) ----------
__device__ float    g_xW[(size_t)NSEQ * T_ * NZ];  // [s*T+t][4096] fwd 0..2047, bwd 2048..4095 (bias incl)
__device__ float    g_h[2][2][NSEQ * UNITS];       // [parity][dir]
__device__ float    g_c[2][NSEQ * UNITS];          // [dir]
__device__ uint32_t g_Upk[2 * 8 * 512 * 256];      // tf32 packed U: [(d*8+hb)*512 + k]*256 + (g*64+hl)

__device__ __forceinline__ float sigm(float x) { return 1.f / (1.f + expf(-x)); }
__device__ __forceinline__ uint32_t f2tf32(float f) {
    uint32_t r; asm("cvt.rna.tf32.f32 %0, %1;" : "=r"(r) : "f"(f)); return r;
}

// ---------------- zero initial state ---------------------------------------
__global__ __launch_bounds__(256) void zero_state() {
    int i = blockIdx.x * 256 + threadIdx.x;
    if (i < NSEQ * UNITS) {
        g_h[0][0][i] = 0.f;
        g_h[0][1][i] = 0.f;
        g_c[0][i]    = 0.f;
        g_c[1][i]    = 0.f;
    }
}

// ---------------- pack U into tf32, gate-blocked layout --------------------
// Upk[((d*8+hb)*512 + k)*256 + g*64 + hl] = tf32(U_d[k][g*512 + hb*64 + hl])
__global__ __launch_bounds__(256) void prep_U(
    const float* __restrict__ U_f, const float* __restrict__ U_b)
{
    int idx = blockIdx.x * 256 + threadIdx.x;     // < 2^21
    int col = idx & 255;
    int k   = (idx >> 8) & 511;
    int hb  = (idx >> 17) & 7;
    int d   = idx >> 20;
    int g   = col >> 6;
    int hl  = col & 63;
    const float* U = d ? U_b : U_f;
    g_Upk[idx] = f2tf32(U[(size_t)k * G4 + g * 512 + hb * 64 + hl]);
}

// ---------------- Phase 1: fused embedding gather + GEMM (fp32) ------------
__global__ __launch_bounds__(256) void embed_gemm(
    const int* __restrict__ x, const float* __restrict__ emb,
    const float* __restrict__ W_f, const float* __restrict__ b_f,
    const float* __restrict__ W_b, const float* __restrict__ b_b)
{
    __shared__ float As[128][20];
    __shared__ float Bs[16][132];
    __shared__ int   ids_s[128];

    const int tid = threadIdx.x;
    const int tx = tid & 15;
    const int ty = tid >> 4;
    const int mBase = blockIdx.y * 128;
    const int nBase = blockIdx.x * 128;

    const float* W  = (nBase < G4) ? W_f : W_b;
    const float* bp = (nBase < G4) ? b_f : b_b;
    const int nOff  = (nBase < G4) ? nBase : (nBase - G4);

    if (tid < 128) ids_s[tid] = x[mBase + tid];
    __syncthreads();

    float acc[8][8] = {};

    for (int k0 = 0; k0 < EMBED; k0 += 16) {
        {
            int lm = tid >> 1;
            int kh = (tid & 1) * 8;
            const float* src = emb + (size_t)ids_s[lm] * EMBED + k0 + kh;
            *(float4*)&As[lm][kh]     = *(const float4*)(src);
            *(float4*)&As[lm][kh + 4] = *(const float4*)(src + 4);
        }
        {
            int kb = tid >> 4;
            int cb = (tid & 15) * 8;
            const float* src = W + (size_t)(k0 + kb) * G4 + nOff + cb;
            *(float4*)&Bs[kb][cb]     = *(const float4*)(src);
            *(float4*)&Bs[kb][cb + 4] = *(const float4*)(src + 4);
        }
        __syncthreads();

        #pragma unroll
        for (int k = 0; k < 16; k++) {
            float a[8], b[8];
            #pragma unroll
            for (int i = 0; i < 8; i++) a[i] = As[ty * 8 + i][k];
            float4 b0 = *(float4*)&Bs[k][tx * 8];
            float4 b1 = *(float4*)&Bs[k][tx * 8 + 4];
            b[0]=b0.x; b[1]=b0.y; b[2]=b0.z; b[3]=b0.w;
            b[4]=b1.x; b[5]=b1.y; b[6]=b1.z; b[7]=b1.w;
            #pragma unroll
            for (int i = 0; i < 8; i++)
                #pragma unroll
                for (int j = 0; j < 8; j++)
                    acc[i][j] = fmaf(a[i], b[j], acc[i][j]);
        }
        __syncthreads();
    }

    #pragma unroll
    for (int i = 0; i < 8; i++) {
        size_t row = (size_t)(mBase + ty * 8 + i);
        float* dst = g_xW + row * NZ + nBase + tx * 8;
        const float* bsrc = bp + nOff + tx * 8;
        #pragma unroll
        for (int j = 0; j < 8; j++) dst[j] = acc[i][j] + bsrc[j];
    }
}

// ---------------- Phase 2: one recurrent step, tf32 tensor-core ------------
// grid (8 rowblk, 8 hb, 2 dir), 256 thr = 8 warps.
// CTA tile: 32 rows x 256 z-cols; warp (wr, g) = rows 16, one gate's 64 hcols.
// z = h_prev @ U (tf32 mma, fp32 acc) + xW; fused gate epilogue with masking.
#define KC 32
#define USTR 264   // sh_u/sh_z row stride (words): 256 + 8 -> conflict-free b-frag loads

__global__ __launch_bounds__(256) void lstm_step_mma(
    const int* __restrict__ x, int sIdx)
{
    const int rb  = blockIdx.x;            // 0..7  (32 rows each)
    const int hb  = blockIdx.y;            // 0..7  (64 hcols each)
    const int dir = blockIdx.z;            // 0 fwd, 1 bwd
    const int parity = sIdx & 1;
    const int t = dir ? (T_ - 1 - sIdx) : sIdx;
    const int rBase = rb * 32;

    __shared__ uint32_t sh_h[32][KC + 4];          // tf32 A tile
    __shared__ union {
        uint32_t u[KC][USTR];                      // tf32 B tile (streamed)
        float    z[32][USTR];                      // acc exchange (reused after K loop)
    } sb;

    const int tid  = threadIdx.x;
    const int wid  = tid >> 5;
    const int lane = tid & 31;
    const int wr   = wid >> 2;             // warp row 0..1 (16 rows)
    const int g    = wid & 3;              // gate = warp col
    const int qr   = lane >> 2;            // 0..7
    const int qc   = lane & 3;             // 0..3

    const float* hin = g_h[parity][dir];
    const uint32_t* upk = g_Upk + ((size_t)(dir * 8 + hb) * 512) * 256;

    float acc[8][4] = {};                  // 8 n8-tiles x 4 regs

    for (int kc = 0; kc < UNITS; kc += KC) {
        // stage h tile: 32 rows x KC, cvt fp32 -> tf32
        {
            int row = tid >> 3;
            int k0  = (tid & 7) * 4;
            float4 v = *(const float4*)&hin[(rBase + row) * UNITS + kc + k0];
            sh_h[row][k0 + 0] = f2tf32(v.x);
            sh_h[row][k0 + 1] = f2tf32(v.y);
            sh_h[row][k0 + 2] = f2tf32(v.z);
            sh_h[row][k0 + 3] = f2tf32(v.w);
        }
        // stage U tile: KC x 256 (already tf32)
        #pragma unroll
        for (int p = 0; p < 8; p++) {
            int q   = p * 1024 + tid * 4;
            int row = q >> 8;
            int col = q & 255;
            *(uint4*)&sb.u[row][col] = *(const uint4*)&upk[(size_t)(kc + row) * 256 + col];
        }
        __syncthreads();

        #pragma unroll
        for (int ks = 0; ks < KC / 8; ks++) {
            uint32_t a0 = sh_h[wr * 16 + qr    ][ks * 8 + qc];
            uint32_t a1 = sh_h[wr * 16 + qr + 8][ks * 8 + qc];
            uint32_t a2 = sh_h[wr * 16 + qr    ][ks * 8 + qc + 4];
            uint32_t a3 = sh_h[wr * 16 + qr + 8][ks * 8 + qc + 4];
            #pragma unroll
            for (int jt = 0; jt < 8; jt++) {
                uint32_t b0 = sb.u[ks * 8 + qc    ][g * 64 + jt * 8 + qr];
                uint32_t b1 = sb.u[ks * 8 + qc + 4][g * 64 + jt * 8 + qr];
                asm volatile(
                    "mma.sync.aligned.m16n8k8.row.col.f32.tf32.tf32.f32 "
                    "{%0,%1,%2,%3},{%4,%5,%6,%7},{%8,%9},{%0,%1,%2,%3};"
                    : "+f"(acc[jt][0]), "+f"(acc[jt][1]), "+f"(acc[jt][2]), "+f"(acc[jt][3])
                    : "r"(a0), "r"(a1), "r"(a2), "r"(a3), "r"(b0), "r"(b1));
            }
        }
        __syncthreads();
    }

    // exchange accs through SMEM: sh_z[row][g*64 + hl]
    #pragma unroll
    for (int jt = 0; jt < 8; jt++) {
        int r0 = wr * 16 + qr;
        int c0 = g * 64 + jt * 8 + qc * 2;
        sb.z[r0    ][c0    ] = acc[jt][0];
        sb.z[r0    ][c0 + 1] = acc[jt][1];
        sb.z[r0 + 8][c0    ] = acc[jt][2];
        sb.z[r0 + 8][c0 + 1] = acc[jt][3];
    }
    __syncthreads();

    // fused gate epilogue: 32x64 (row, hl) elems, 8 per thread
    float* hout = g_h[parity ^ 1][dir];
    float* c    = g_c[dir];
    #pragma unroll
    for (int e = 0; e < 8; e++) {
        int idx = e * 256 + tid;
        int row = idx >> 6;
        int hl  = idx & 63;
        int s   = rBase + row;
        bool m  = (x[s * T_ + t] != 0);
        const float* xw = g_xW + ((size_t)s * T_ + t) * NZ + dir * G4 + hb * 64 + hl;
        float zi = sb.z[row][0 * 64 + hl] + xw[0];
        float zf = sb.z[row][1 * 64 + hl] + xw[512];
        float zg = sb.z[row][2 * 64 + hl] + xw[1024];
        float zo = sb.z[row][3 * 64 + hl] + xw[1536];
        float ig = sigm(zi), fg = sigm(zf);
        float gg = tanhf(zg), og = sigm(zo);
        int hidx = s * UNITS + hb * 64 + hl;
        float cold = c[hidx];
        float cnew = fg * cold + ig * gg;
        float hnew = og * tanhf(cnew);
        if (m) c[hidx] = cnew;
        hout[hidx] = m ? hnew : hin[hidx];
    }
}

// ---------------- output: concat [h_fwd | h_bwd] ---------------------------
__global__ __launch_bounds__(256) void write_out(float* __restrict__ out) {
    int i = blockIdx.x * 256 + threadIdx.x;
    int s = i >> 10;
    int u = i & 1023;
    float v = (u < 512) ? g_h[0][0][s * 512 + u]
                        : g_h[0][1][s * 512 + (u - 512)];
    out[i] = v;
}

// ---------------- launcher -------------------------------------------------
extern "C" void kernel_launch(void* const* d_in, const int* in_sizes, int n_in,
                              void* d_out, int out_size)
{
    const int*   x   = (const int*)  d_in[0];
    const float* emb = (const float*)d_in[1];
    const float* W_f = (const float*)d_in[2];
    const float* U_f = (const float*)d_in[3];
    const float* b_f = (const float*)d_in[4];
    const float* W_b = (const float*)d_in[5];
    const float* U_b = (const float*)d_in[6];
    const float* b_b = (const float*)d_in[7];
    float* out = (float*)d_out;

    zero_state<<<(NSEQ * UNITS + 255) / 256, 256>>>();
    prep_U<<<(2 * 8 * 512 * 256) / 256, 256>>>(U_f, U_b);
    embed_gemm<<<dim3(NZ / 128, (NSEQ * T_) / 128), 256>>>(x, emb, W_f, b_f, W_b, b_b);
    for (int s = 0; s < T_; s++)
        lstm_step_mma<<<dim3(8, 8, 2), 256>>>(x, s);
    write_out<<<(NSEQ * 1024) / 256, 256>>>(out);
}

// round 4
// speedup vs baseline: 1.8919x; 1.2965x over previous
#include <cuda_runtime.h>
#include <cuda_fp16.h>
#include <math.h>
#include <stdint.h>

// Problem constants
#define T_     128
#define NSEQ   256          // B*S
#define EMBED  512
#define UNITS  512
#define G4     2048         // 4*UNITS
#define NZ     4096         // both directions
#define NCTA   128

// ---------------- scratch (device globals) ---------------------------------
__device__ float    g_xW[(size_t)NSEQ * T_ * NZ];  // [s*T+t][4096] fwd|bwd, bias included
__device__ float    g_h[2][2][NSEQ * UNITS];       // [parity][dir]
__device__ float    g_c[2][NSEQ * UNITS];          // [dir]
__device__ uint32_t g_Upk[2 * 16 * 32768];         // fp16 frag-packed U per (dir,cb) slice
__device__ unsigned g_bar_count = 0;
__device__ unsigned g_bar_gen   = 0;

__device__ __forceinline__ float sigm(float x) { return 1.f / (1.f + expf(-x)); }

// ---------------- grid-wide barrier (all 128 CTAs resident) ----------------
__device__ __forceinline__ void grid_sync() {
    __syncthreads();
    if (threadIdx.x == 0) {
        __threadfence();
        volatile unsigned* genp = &g_bar_gen;
        unsigned gen = *genp;
        if (atomicAdd(&g_bar_count, 1u) == NCTA - 1) {
            g_bar_count = 0;
            __threadfence();
            *genp = gen + 1;
        } else {
            while (*genp == gen) { __nanosleep(32); }
            __threadfence();
        }
    }
    __syncthreads();
}

// ---------------- pack U into fp16 MMA-fragment order ----------------------
// Slice (dir, cb): B[k][n] = U[k][g*512 + cb*32 + hl], n = g*32+hl (128 zcols).
// Word layout: [kb 32][np 8][lane 32][4 words]; word (sub*2+wi) holds
// k = kb*16 + wi*8 + 2qc (+1), n = (np*2+sub)*8 + qr. lane = qr*4+qc.
__global__ __launch_bounds__(256) void prep_U(
    const float* __restrict__ U_f, const float* __restrict__ U_b)
{
    int widx  = blockIdx.x * 256 + threadIdx.x;   // < 2^20
    int word  = widx & 32767;
    int slice = widx >> 15;
    int dir = slice >> 4, cb = slice & 15;
    int kb   = word >> 10;
    int np   = (word >> 7) & 7;
    int lane = (word >> 2) & 31;
    int q    = word & 3;
    int sub = q >> 1, wi = q & 1;
    int qr = lane >> 2, qc = lane & 3;
    int n = (np * 2 + sub) * 8 + qr;
    int k = kb * 16 + wi * 8 + 2 * qc;
    int col = (n >> 5) * 512 + cb * 32 + (n & 31);
    const float* U = dir ? U_b : U_f;
    float lo = U[(size_t)k * G4 + col];
    float hi = U[(size_t)(k + 1) * G4 + col];
    half2 h2 = __floats2half2_rn(lo, hi);
    g_Upk[widx] = *(uint32_t*)&h2;
}

// ---------------- Phase 1: fused embedding gather + GEMM (fp32) ------------
__global__ __launch_bounds__(256) void embed_gemm(
    const int* __restrict__ x, const float* __restrict__ emb,
    const float* __restrict__ W_f, const float* __restrict__ b_f,
    const float* __restrict__ W_b, const float* __restrict__ b_b)
{
    __shared__ float As[128][20];
    __shared__ float Bs[16][132];
    __shared__ int   ids_s[128];

    const int tid = threadIdx.x;
    const int tx = tid & 15;
    const int ty = tid >> 4;
    const int mBase = blockIdx.y * 128;
    const int nBase = blockIdx.x * 128;

    const float* W  = (nBase < G4) ? W_f : W_b;
    const float* bp = (nBase < G4) ? b_f : b_b;
    const int nOff  = (nBase < G4) ? nBase : (nBase - G4);

    if (tid < 128) ids_s[tid] = x[mBase + tid];
    __syncthreads();

    float acc[8][8] = {};

    for (int k0 = 0; k0 < EMBED; k0 += 16) {
        {
            int lm = tid >> 1;
            int kh = (tid & 1) * 8;
            const float* src = emb + (size_t)ids_s[lm] * EMBED + k0 + kh;
            *(float4*)&As[lm][kh]     = *(const float4*)(src);
            *(float4*)&As[lm][kh + 4] = *(const float4*)(src + 4);
        }
        {
            int kb = tid >> 4;
            int cbv = (tid & 15) * 8;
            const float* src = W + (size_t)(k0 + kb) * G4 + nOff + cbv;
            *(float4*)&Bs[kb][cbv]     = *(const float4*)(src);
            *(float4*)&Bs[kb][cbv + 4] = *(const float4*)(src + 4);
        }
        __syncthreads();

        #pragma unroll
        for (int k = 0; k < 16; k++) {
            float a[8], b[8];
            #pragma unroll
            for (int i = 0; i < 8; i++) a[i] = As[ty * 8 + i][k];
            float4 b0 = *(float4*)&Bs[k][tx * 8];
            float4 b1 = *(float4*)&Bs[k][tx * 8 + 4];
            b[0]=b0.x; b[1]=b0.y; b[2]=b0.z; b[3]=b0.w;
            b[4]=b1.x; b[5]=b1.y; b[6]=b1.z; b[7]=b1.w;
            #pragma unroll
            for (int i = 0; i < 8; i++)
                #pragma unroll
                for (int j = 0; j < 8; j++)
                    acc[i][j] = fmaf(a[i], b[j], acc[i][j]);
        }
        __syncthreads();
    }

    #pragma unroll
    for (int i = 0; i < 8; i++) {
        size_t row = (size_t)(mBase + ty * 8 + i);
        float* dst = g_xW + row * NZ + nBase + tx * 8;
        const float* bsrc = bp + nOff + tx * 8;
        #pragma unroll
        for (int j = 0; j < 8; j++) dst[j] = acc[i][j] + bsrc[j];
    }
}

// ---------------- Phase 2: persistent bidirectional LSTM -------------------
// 128 CTAs x 256 thr. CTA (dir, cb, rb): 64 rows x 128 zcols (4 gates x 32 h).
// U slice fp16 resident in SMEM for all 128 steps. fp16 MMA, fp32 accum.
#define HSTR 520   // h staging row stride in halves
#define ZSTR 132   // z exchange row stride in floats

#define MMA16816(d, a, b0v, b1v)                                              \
    asm volatile(                                                             \
        "mma.sync.aligned.m16n8k16.row.col.f32.f16.f16.f32 "                  \
        "{%0,%1,%2,%3},{%4,%5,%6,%7},{%8,%9},{%0,%1,%2,%3};"                  \
        : "+f"(d[0]), "+f"(d[1]), "+f"(d[2]), "+f"(d[3])                      \
        : "r"(a[0]), "r"(a[1]), "r"(a[2]), "r"(a[3]), "r"(b0v), "r"(b1v))

#define LDSM4(r, addr)                                                        \
    asm volatile("ldmatrix.sync.aligned.m8n8.x4.shared.b16 "                  \
                 "{%0,%1,%2,%3}, [%4];"                                       \
                 : "=r"(r[0]), "=r"(r[1]), "=r"(r[2]), "=r"(r[3])             \
                 : "r"(addr))

extern __shared__ char smem_dyn[];

__global__ __launch_bounds__(256, 1) void lstm_persist(
    const int* __restrict__ x, float* __restrict__ out)
{
    uint32_t* uB = (uint32_t*)smem_dyn;                    // 128 KB
    __half*   hA = (__half*)(smem_dyn + 131072);           // 64 x HSTR halves
    float*   shZ = (float*)(smem_dyn + 131072);            // alias (post-sync)

    const int tid  = threadIdx.x;
    const int lane = tid & 31;
    const int wid  = tid >> 5;
    const int bid  = blockIdx.x;
    const int dir  = bid >> 6;
    const int cb   = (bid >> 2) & 15;
    const int rb   = bid & 3;
    const int rBase  = rb * 64;
    const int cbBase = cb * 32;

    // Load U slice once (resident for all steps)
    {
        const uint4* src = (const uint4*)(g_Upk + (size_t)(dir * 16 + cb) * 32768);
        uint4* dst = (uint4*)uB;
        #pragma unroll
        for (int i = 0; i < 32; i++) dst[i * 256 + tid] = src[i * 256 + tid];
    }
    // Zero this CTA's c and h[0] slices
    #pragma unroll
    for (int e = 0; e < 8; e++) {
        int row = e * 8 + wid;
        int hidx = (rBase + row) * UNITS + cbBase + lane;
        g_c[dir][hidx]    = 0.f;
        g_h[0][dir][hidx] = 0.f;
    }

    const int wm = wid >> 2;          // 0..1 : 32 rows
    const int wn = wid & 3;           // 0..3 : 32 zcols
    const int qr = lane >> 2, qc = lane & 3;

    // ldmatrix lane addresses (A frags, row-major h staging)
    int lm_row = (lane & 7) + ((lane >> 3) & 1) * 8;   // 0..15
    int lm_kh  = (lane >> 4) * 8;                      // 0 or 8 halves
    uint32_t hA_s = (uint32_t)__cvta_generic_to_shared(hA);
    uint32_t lmaddr0 = hA_s + (uint32_t)(((wm * 32 + 0  + lm_row) * HSTR + lm_kh) * 2);
    uint32_t lmaddr1 = hA_s + (uint32_t)(((wm * 32 + 16 + lm_row) * HSTR + lm_kh) * 2);

    for (int sstep = 0; sstep < T_; sstep++) {
        grid_sync();
        const int t = dir ? (T_ - 1 - sstep) : sstep;
        const int parity = sstep & 1;
        const float* hin  = g_h[parity][dir];
        float*       hout = g_h[parity ^ 1][dir];

        // Prefetch this step's xW (coalesced; hides DRAM latency under K loop)
        float xwp[8][4];
        #pragma unroll
        for (int e = 0; e < 8; e++) {
            int row = e * 8 + wid;
            const float* p = g_xW + ((size_t)(rBase + row) * T_ + t) * NZ
                           + dir * G4 + cbBase + lane;
            #pragma unroll
            for (int g = 0; g < 4; g++) xwp[e][g] = p[g * 512];
        }

        // Stage h tile (64 rows x 512) fp32 -> fp16, row-major
        {
            int row = tid >> 2, seg = tid & 3;
            const float* src = hin + (rBase + row) * UNITS + seg * 128;
            __half* d = hA + row * HSTR + seg * 128;
            #pragma unroll
            for (int i = 0; i < 32; i++) {
                float4 v = *(const float4*)(src + i * 4);
                *(half2*)(d + i * 4)     = __floats2half2_rn(v.x, v.y);
                *(half2*)(d + i * 4 + 2) = __floats2half2_rn(v.z, v.w);
            }
        }
        __syncthreads();

        // K loop: z = h @ U  (fp16 MMA, fp32 accum)
        float acc[2][4][4];
        #pragma unroll
        for (int mt = 0; mt < 2; mt++)
            #pragma unroll
            for (int nt = 0; nt < 4; nt++)
                #pragma unroll
                for (int r = 0; r < 4; r++) acc[mt][nt][r] = 0.f;

        #pragma unroll 4
        for (int kb = 0; kb < 32; kb++) {
            uint32_t a0[4], a1[4];
            LDSM4(a0, lmaddr0 + kb * 32);
            LDSM4(a1, lmaddr1 + kb * 32);
            uint4 B0 = *(const uint4*)&uB[((kb * 8 + wn * 2    ) * 32 + lane) * 4];
            uint4 B1 = *(const uint4*)&uB[((kb * 8 + wn * 2 + 1) * 32 + lane) * 4];
            MMA16816(acc[0][0], a0, B0.x, B0.y);
            MMA16816(acc[0][1], a0, B0.z, B0.w);
            MMA16816(acc[0][2], a0, B1.x, B1.y);
            MMA16816(acc[0][3], a0, B1.z, B1.w);
            MMA16816(acc[1][0], a1, B0.x, B0.y);
            MMA16816(acc[1][1], a1, B0.z, B0.w);
            MMA16816(acc[1][2], a1, B1.x, B1.y);
            MMA16816(acc[1][3], a1, B1.z, B1.w);
        }
        __syncthreads();   // done reading hA; reuse region for z

        // Exchange accumulators through SMEM: shZ[row][n]
        #pragma unroll
        for (int mt = 0; mt < 2; mt++)
            #pragma unroll
            for (int nt = 0; nt < 4; nt++) {
                int row0 = wm * 32 + mt * 16 + qr;
                int col  = wn * 32 + nt * 8 + qc * 2;
                *(float2*)&shZ[row0 * ZSTR + col] =
                    make_float2(acc[mt][nt][0], acc[mt][nt][1]);
                *(float2*)&shZ[(row0 + 8) * ZSTR + col] =
                    make_float2(acc[mt][nt][2], acc[mt][nt][3]);
            }
        __syncthreads();

        // Fused gate epilogue with Keras masking (hold state where id==0)
        #pragma unroll
        for (int e = 0; e < 8; e++) {
            int row = e * 8 + wid;
            int hl  = lane;
            int s   = rBase + row;
            bool m  = (x[s * T_ + t] != 0);
            float zi = shZ[row * ZSTR +       hl] + xwp[e][0];
            float zf = shZ[row * ZSTR +  32 + hl] + xwp[e][1];
            float zg = shZ[row * ZSTR +  64 + hl] + xwp[e][2];
            float zo = shZ[row * ZSTR +  96 + hl] + xwp[e][3];
            float ig = sigm(zi), fg = sigm(zf);
            float gg = tanhf(zg), og = sigm(zo);
            int hidx = s * UNITS + cbBase + hl;
            float cold = g_c[dir][hidx];
            float cnew = fg * cold + ig * gg;
            float hnew = og * tanhf(cnew);
            if (m) g_c[dir][hidx] = cnew;
            hout[hidx] = m ? hnew : hin[hidx];
        }
    }

    grid_sync();
    // Output: out[s][dir*512 + hcol] = final h (parity 0 after 128 steps)
    #pragma unroll
    for (int e = 0; e < 8; e++) {
        int row = e * 8 + wid;
        int s = rBase + row;
        out[s * 1024 + dir * 512 + cbBase + lane] =
            g_h[0][dir][s * UNITS + cbBase + lane];
    }
}

// ---------------- launcher -------------------------------------------------
extern "C" void kernel_launch(void* const* d_in, const int* in_sizes, int n_in,
                              void* d_out, int out_size)
{
    const int*   x   = (const int*)  d_in[0];
    const float* emb = (const float*)d_in[1];
    const float* W_f = (const float*)d_in[2];
    const float* U_f = (const float*)d_in[3];
    const float* b_f = (const float*)d_in[4];
    const float* W_b = (const float*)d_in[5];
    const float* U_b = (const float*)d_in[6];
    const float* b_b = (const float*)d_in[7];
    float* out = (float*)d_out;

    cudaFuncSetAttribute(lstm_persist,
                         cudaFuncAttributeMaxDynamicSharedMemorySize, 197632);

    prep_U<<<(2 * 16 * 32768) / 256, 256>>>(U_f, U_b);
    embed_gemm<<<dim3(NZ / 128, (NSEQ * T_) / 128), 256>>>(x, emb, W_f, b_f, W_b, b_b);
    lstm_persist<<<NCTA, 256, 197632>>>(x, out);
}

// round 5
// speedup vs baseline: 3.9862x; 2.1069x over previous
#include <cuda_runtime.h>
#include <cuda_fp16.h>
#include <math.h>
#include <stdint.h>

// Problem constants
#define T_     128
#define NSEQ   256          // B*S
#define EMBED  512
#define UNITS  512
#define G4     2048         // 4*UNITS
#define NZ     4096         // both directions
#define NCTA   128

// ---------------- scratch (device globals) ---------------------------------
__device__ __half   g_xW[(size_t)NSEQ * T_ * NZ];  // fp16 [s*T+t][4096] fwd|bwd, bias incl
__device__ float    g_h[2][2][NSEQ * UNITS];       // [parity][dir]
__device__ float    g_c[2][NSEQ * UNITS];          // [dir]
__device__ uint32_t g_Upk[2 * 16 * 32768];         // fp16 frag-packed U per (dir,cb) slice
__device__ uint32_t g_Wpk[32 * 32768];             // fp16 frag-packed [W_f|W_b] per 128-col slice
__device__ unsigned g_bar_count = 0;
__device__ unsigned g_bar_gen   = 0;

__device__ __forceinline__ float sigm(float x) { return 1.f / (1.f + expf(-x)); }

// ---------------- grid-wide barrier (all 128 CTAs resident) ----------------
__device__ __forceinline__ void grid_sync() {
    __syncthreads();
    if (threadIdx.x == 0) {
        __threadfence();
        volatile unsigned* genp = &g_bar_gen;
        unsigned gen = *genp;
        if (atomicAdd(&g_bar_count, 1u) == NCTA - 1) {
            g_bar_count = 0;
            __threadfence();
            *genp = gen + 1;
        } else {
            while (*genp == gen) { __nanosleep(32); }
            __threadfence();
        }
    }
    __syncthreads();
}

// ---------------- pack U into fp16 MMA-fragment order ----------------------
// Slice (dir, cb): B[k][n] = U[k][g*512 + cb*32 + hl], n = g*32+hl (128 zcols).
// Word layout: [kb 32][np 8][lane 32][4 words]; word (sub*2+wi) holds
// k = kb*16 + wi*8 + 2qc (+1), n = (np*2+sub)*8 + qr. lane = qr*4+qc.
__global__ __launch_bounds__(256) void prep_U(
    const float* __restrict__ U_f, const float* __restrict__ U_b)
{
    int widx  = blockIdx.x * 256 + threadIdx.x;   // < 2^20
    int word  = widx & 32767;
    int slice = widx >> 15;
    int dir = slice >> 4, cb = slice & 15;
    int kb   = word >> 10;
    int np   = (word >> 7) & 7;
    int lane = (word >> 2) & 31;
    int q    = word & 3;
    int sub = q >> 1, wi = q & 1;
    int qr = lane >> 2, qc = lane & 3;
    int n = (np * 2 + sub) * 8 + qr;
    int k = kb * 16 + wi * 8 + 2 * qc;
    int col = (n >> 5) * 512 + cb * 32 + (n & 31);
    const float* U = dir ? U_b : U_f;
    float lo = U[(size_t)k * G4 + col];
    float hi = U[(size_t)(k + 1) * G4 + col];
    half2 h2 = __floats2half2_rn(lo, hi);
    g_Upk[widx] = *(uint32_t*)&h2;
}

// ---------------- pack [W_f|W_b] into same fragment order ------------------
// Slice nb (0..31): 128 global z-cols [nb*128, nb*128+128). c<2048 -> W_f else W_b.
__global__ __launch_bounds__(256) void prep_W(
    const float* __restrict__ W_f, const float* __restrict__ W_b)
{
    int widx  = blockIdx.x * 256 + threadIdx.x;   // < 2^20
    int word  = widx & 32767;
    int nb    = widx >> 15;
    int kb   = word >> 10;
    int np   = (word >> 7) & 7;
    int lane = (word >> 2) & 31;
    int q    = word & 3;
    int sub = q >> 1, wi = q & 1;
    int qr = lane >> 2, qc = lane & 3;
    int nl = (np * 2 + sub) * 8 + qr;
    int k  = kb * 16 + wi * 8 + 2 * qc;
    int c  = nb * 128 + nl;
    const float* W = (c < G4) ? (W_f + c) : (W_b + c - G4);
    float lo = W[(size_t)k * G4];
    float hi = W[(size_t)(k + 1) * G4];
    half2 h2 = __floats2half2_rn(lo, hi);
    g_Wpk[widx] = *(uint32_t*)&h2;
}

// ---------------- MMA helpers ----------------------------------------------
#define MMA16816(d, a, b0v, b1v)                                              \
    asm volatile(                                                             \
        "mma.sync.aligned.m16n8k16.row.col.f32.f16.f16.f32 "                  \
        "{%0,%1,%2,%3},{%4,%5,%6,%7},{%8,%9},{%0,%1,%2,%3};"                  \
        : "+f"(d[0]), "+f"(d[1]), "+f"(d[2]), "+f"(d[3])                      \
        : "r"(a[0]), "r"(a[1]), "r"(a[2]), "r"(a[3]), "r"(b0v), "r"(b1v))

#define LDSM4(r, addr)                                                        \
    asm volatile("ldmatrix.sync.aligned.m8n8.x4.shared.b16 "                  \
                 "{%0,%1,%2,%3}, [%4];"                                       \
                 : "=r"(r[0]), "=r"(r[1]), "=r"(r[2]), "=r"(r[3])             \
                 : "r"(addr))

extern __shared__ char smem_dyn[];

// ---------------- Phase 1: fused gather + fp16 tensor-core GEMM ------------
// grid (16, 256). CTA: 128 rows x 256 z-cols, K=512 fully staged in SMEM.
// Warp (wm 0..3, wn 0..1): 32 rows x 128 cols (slice nb = 2*bx + wn).
#define ESTR 520   // A staging row stride in halves

__global__ __launch_bounds__(256, 1) void embed_mma(
    const int* __restrict__ x, const float* __restrict__ emb,
    const float* __restrict__ b_f, const float* __restrict__ b_b)
{
    __shared__ int ids_s[128];
    __half* hA = (__half*)smem_dyn;                // 128 x ESTR halves

    const int tid  = threadIdx.x;
    const int lane = tid & 31;
    const int wid  = tid >> 5;
    const int wm   = wid >> 1;          // 0..3 : 32 rows
    const int wn   = wid & 1;           // 0..1 : 128 cols
    const int qr = lane >> 2, qc = lane & 3;
    const int mBase = blockIdx.y * 128;
    const int nb    = blockIdx.x * 2 + wn;

    if (tid < 128) ids_s[tid] = x[mBase + tid];
    __syncthreads();

    // Stage full A tile: 128 rows x 512 k, fp32 -> fp16
    {
        int row = tid >> 1, seg = tid & 1;
        const float* src = emb + (size_t)ids_s[row] * EMBED + seg * 256;
        __half* d = hA + row * ESTR + seg * 256;
        #pragma unroll
        for (int i = 0; i < 64; i++) {
            float4 v = *(const float4*)(src + i * 4);
            *(half2*)(d + i * 4)     = __floats2half2_rn(v.x, v.y);
            *(half2*)(d + i * 4 + 2) = __floats2half2_rn(v.z, v.w);
        }
    }
    __syncthreads();

    int lm_row = (lane & 7) + ((lane >> 3) & 1) * 8;
    int lm_kh  = (lane >> 4) * 8;
    uint32_t hA_s = (uint32_t)__cvta_generic_to_shared(hA);
    uint32_t lmaddr0 = hA_s + (uint32_t)(((wm * 32 + 0  + lm_row) * ESTR + lm_kh) * 2);
    uint32_t lmaddr1 = hA_s + (uint32_t)(((wm * 32 + 16 + lm_row) * ESTR + lm_kh) * 2);

    const uint32_t* gW = g_Wpk + (size_t)nb * 32768;

    float acc[2][16][4];
    #pragma unroll
    for (int mt = 0; mt < 2; mt++)
        #pragma unroll
        for (int j = 0; j < 16; j++)
            #pragma unroll
            for (int r = 0; r < 4; r++) acc[mt][j][r] = 0.f;

    #pragma unroll 2
    for (int kb = 0; kb < 32; kb++) {
        uint32_t a0[4], a1[4];
        LDSM4(a0, lmaddr0 + kb * 32);
        LDSM4(a1, lmaddr1 + kb * 32);
        uint4 Bv[8];
        #pragma unroll
        for (int np = 0; np < 8; np++)
            Bv[np] = *(const uint4*)&gW[(((kb * 8 + np) * 32 + lane) << 2)];
        #pragma unroll
        for (int j = 0; j < 16; j++) {
            uint32_t b0 = (j & 1) ? Bv[j >> 1].z : Bv[j >> 1].x;
            uint32_t b1 = (j & 1) ? Bv[j >> 1].w : Bv[j >> 1].y;
            MMA16816(acc[0][j], a0, b0, b1);
            MMA16816(acc[1][j], a1, b0, b1);
        }
    }

    // Epilogue: add bias, store fp16 z to g_xW
    const float* bp = (nb < 16) ? (b_f + nb * 128) : (b_b + nb * 128 - G4);
    #pragma unroll
    for (int mt = 0; mt < 2; mt++) {
        #pragma unroll
        for (int j = 0; j < 16; j++) {
            int row = mBase + wm * 32 + mt * 16 + qr;
            int cl  = j * 8 + qc * 2;
            float bx = bp[cl], by = bp[cl + 1];
            half2 lo = __floats2half2_rn(acc[mt][j][0] + bx, acc[mt][j][1] + by);
            half2 hi = __floats2half2_rn(acc[mt][j][2] + bx, acc[mt][j][3] + by);
            *(half2*)&g_xW[(size_t)row * NZ + nb * 128 + cl]       = lo;
            *(half2*)&g_xW[(size_t)(row + 8) * NZ + nb * 128 + cl] = hi;
        }
    }
}

// ---------------- Phase 2: persistent bidirectional LSTM -------------------
#define HSTR 520   // h staging row stride in halves
#define ZSTR 132   // z exchange row stride in floats

__global__ __launch_bounds__(256, 1) void lstm_persist(
    const int* __restrict__ x, float* __restrict__ out)
{
    uint32_t* uB = (uint32_t*)smem_dyn;                    // 128 KB
    __half*   hA = (__half*)(smem_dyn + 131072);           // 64 x HSTR halves
    float*   shZ = (float*)(smem_dyn + 131072);            // alias (post-sync)

    const int tid  = threadIdx.x;
    const int lane = tid & 31;
    const int wid  = tid >> 5;
    const int bid  = blockIdx.x;
    const int dir  = bid >> 6;
    const int cb   = (bid >> 2) & 15;
    const int rb   = bid & 3;
    const int rBase  = rb * 64;
    const int cbBase = cb * 32;

    // Load U slice once (resident for all steps)
    {
        const uint4* src = (const uint4*)(g_Upk + (size_t)(dir * 16 + cb) * 32768);
        uint4* dst = (uint4*)uB;
        #pragma unroll
        for (int i = 0; i < 32; i++) dst[i * 256 + tid] = src[i * 256 + tid];
    }
    // Zero this CTA's c and h[0] slices
    #pragma unroll
    for (int e = 0; e < 8; e++) {
        int row = e * 8 + wid;
        int hidx = (rBase + row) * UNITS + cbBase + lane;
        g_c[dir][hidx]    = 0.f;
        g_h[0][dir][hidx] = 0.f;
    }

    const int wm = wid >> 2;
    const int wn = wid & 3;
    const int qr = lane >> 2, qc = lane & 3;

    int lm_row = (lane & 7) + ((lane >> 3) & 1) * 8;
    int lm_kh  = (lane >> 4) * 8;
    uint32_t hA_s = (uint32_t)__cvta_generic_to_shared(hA);
    uint32_t lmaddr0 = hA_s + (uint32_t)(((wm * 32 + 0  + lm_row) * HSTR + lm_kh) * 2);
    uint32_t lmaddr1 = hA_s + (uint32_t)(((wm * 32 + 16 + lm_row) * HSTR + lm_kh) * 2);

    for (int sstep = 0; sstep < T_; sstep++) {
        grid_sync();
        const int t = dir ? (T_ - 1 - sstep) : sstep;
        const int parity = sstep & 1;
        const float* hin  = g_h[parity][dir];
        float*       hout = g_h[parity ^ 1][dir];

        // Prefetch this step's xW (fp16)
        float xwp[8][4];
        #pragma unroll
        for (int e = 0; e < 8; e++) {
            int row = e * 8 + wid;
            const __half* p = g_xW + ((size_t)(rBase + row) * T_ + t) * NZ
                            + dir * G4 + cbBase + lane;
            #pragma unroll
            for (int g = 0; g < 4; g++) xwp[e][g] = __half2float(p[g * 512]);
        }

        // Stage h tile (64 rows x 512) fp32 -> fp16
        {
            int row = tid >> 2, seg = tid & 3;
            const float* src = hin + (rBase + row) * UNITS + seg * 128;
            __half* d = hA + row * HSTR + seg * 128;
            #pragma unroll
            for (int i = 0; i < 32; i++) {
                float4 v = *(const float4*)(src + i * 4);
                *(half2*)(d + i * 4)     = __floats2half2_rn(v.x, v.y);
                *(half2*)(d + i * 4 + 2) = __floats2half2_rn(v.z, v.w);
            }
        }
        __syncthreads();

        float acc[2][4][4];
        #pragma unroll
        for (int mt = 0; mt < 2; mt++)
            #pragma unroll
            for (int nt = 0; nt < 4; nt++)
                #pragma unroll
                for (int r = 0; r < 4; r++) acc[mt][nt][r] = 0.f;

        #pragma unroll 4
        for (int kb = 0; kb < 32; kb++) {
            uint32_t a0[4], a1[4];
            LDSM4(a0, lmaddr0 + kb * 32);
            LDSM4(a1, lmaddr1 + kb * 32);
            uint4 B0 = *(const uint4*)&uB[((kb * 8 + wn * 2    ) * 32 + lane) * 4];
            uint4 B1 = *(const uint4*)&uB[((kb * 8 + wn * 2 + 1) * 32 + lane) * 4];
            MMA16816(acc[0][0], a0, B0.x, B0.y);
            MMA16816(acc[0][1], a0, B0.z, B0.w);
            MMA16816(acc[0][2], a0, B1.x, B1.y);
            MMA16816(acc[0][3], a0, B1.z, B1.w);
            MMA16816(acc[1][0], a1, B0.x, B0.y);
            MMA16816(acc[1][1], a1, B0.z, B0.w);
            MMA16816(acc[1][2], a1, B1.x, B1.y);
            MMA16816(acc[1][3], a1, B1.z, B1.w);
        }
        __syncthreads();

        #pragma unroll
        for (int mt = 0; mt < 2; mt++)
            #pragma unroll
            for (int nt = 0; nt < 4; nt++) {
                int row0 = wm * 32 + mt * 16 + qr;
                int col  = wn * 32 + nt * 8 + qc * 2;
                *(float2*)&shZ[row0 * ZSTR + col] =
                    make_float2(acc[mt][nt][0], acc[mt][nt][1]);
                *(float2*)&shZ[(row0 + 8) * ZSTR + col] =
                    make_float2(acc[mt][nt][2], acc[mt][nt][3]);
            }
        __syncthreads();

        // Fused gate epilogue with Keras masking
        #pragma unroll
        for (int e = 0; e < 8; e++) {
            int row = e * 8 + wid;
            int hl  = lane;
            int s   = rBase + row;
            bool m  = (x[s * T_ + t] != 0);
            float zi = shZ[row * ZSTR +       hl] + xwp[e][0];
            float zf = shZ[row * ZSTR +  32 + hl] + xwp[e][1];
            float zg = shZ[row * ZSTR +  64 + hl] + xwp[e][2];
            float zo = shZ[row * ZSTR +  96 + hl] + xwp[e][3];
            float ig = sigm(zi), fg = sigm(zf);
            float gg = tanhf(zg), og = sigm(zo);
            int hidx = s * UNITS + cbBase + hl;
            float cold = g_c[dir][hidx];
            float cnew = fg * cold + ig * gg;
            float hnew = og * tanhf(cnew);
            if (m) g_c[dir][hidx] = cnew;
            hout[hidx] = m ? hnew : hin[hidx];
        }
    }

    grid_sync();
    #pragma unroll
    for (int e = 0; e < 8; e++) {
        int row = e * 8 + wid;
        int s = rBase + row;
        out[s * 1024 + dir * 512 + cbBase + lane] =
            g_h[0][dir][s * UNITS + cbBase + lane];
    }
}

// ---------------- launcher -------------------------------------------------
extern "C" void kernel_launch(void* const* d_in, const int* in_sizes, int n_in,
                              void* d_out, int out_size)
{
    const int*   x   = (const int*)  d_in[0];
    const float* emb = (const float*)d_in[1];
    const float* W_f = (const float*)d_in[2];
    const float* U_f = (const float*)d_in[3];
    const float* b_f = (const float*)d_in[4];
    const float* W_b = (const float*)d_in[5];
    const float* U_b = (const float*)d_in[6];
    const float* b_b = (const float*)d_in[7];
    float* out = (float*)d_out;

    cudaFuncSetAttribute(embed_mma,
                         cudaFuncAttributeMaxDynamicSharedMemorySize, 133120);
    cudaFuncSetAttribute(lstm_persist,
                         cudaFuncAttributeMaxDynamicSharedMemorySize, 197632);

    prep_U<<<(2 * 16 * 32768) / 256, 256>>>(U_f, U_b);
    prep_W<<<(32 * 32768) / 256, 256>>>(W_f, W_b);
    embed_mma<<<dim3(16, 256), 256, 133120>>>(x, emb, b_f, b_b);
    lstm_persist<<<NCTA, 256, 197632>>>(x, out);
}

// round 6
// speedup vs baseline: 5.6671x; 1.4217x over previous
#include <cuda_runtime.h>
#include <cuda_fp16.h>
#include <math.h>
#include <stdint.h>

// Problem constants
#define T_     128
#define NSEQ   256          // B*S
#define EMBED  512
#define UNITS  512
#define G4     2048         // 4*UNITS
#define NZ     4096         // both directions
#define NCTA   128

// ---------------- scratch (device globals) ---------------------------------
__device__ __half   g_xW[(size_t)NSEQ * T_ * NZ];  // fp16 [s*T+t][4096] fwd|bwd, bias incl
__device__ __half   g_h16[2][2][NSEQ * UNITS];     // fp16 h, [parity][dir]
__device__ uint32_t g_Upk[2 * 16 * 32768];         // fp16 frag-packed U per (dir,cb) slice
__device__ uint32_t g_Wpk[32 * 32768];             // fp16 frag-packed [W_f|W_b] per 128-col slice
__device__ unsigned g_bar_count = 0;
__device__ unsigned g_bar_gen   = 0;

__device__ __forceinline__ float sigm(float x) { return 1.f / (1.f + expf(-x)); }

// ---------------- grid-wide barrier (all 128 CTAs resident) ----------------
__device__ __forceinline__ void grid_sync() {
    __syncthreads();
    if (threadIdx.x == 0) {
        __threadfence();
        volatile unsigned* genp = &g_bar_gen;
        unsigned gen = *genp;
        if (atomicAdd(&g_bar_count, 1u) == NCTA - 1) {
            g_bar_count = 0;
            __threadfence();
            *genp = gen + 1;
        } else {
            while (*genp == gen) { __nanosleep(32); }
            __threadfence();
        }
    }
    __syncthreads();
}

// ---------------- pack U into fp16 MMA-fragment order ----------------------
__global__ __launch_bounds__(256) void prep_U(
    const float* __restrict__ U_f, const float* __restrict__ U_b)
{
    int widx  = blockIdx.x * 256 + threadIdx.x;   // < 2^20
    int word  = widx & 32767;
    int slice = widx >> 15;
    int dir = slice >> 4, cb = slice & 15;
    int kb   = word >> 10;
    int np   = (word >> 7) & 7;
    int lane = (word >> 2) & 31;
    int q    = word & 3;
    int sub = q >> 1, wi = q & 1;
    int qr = lane >> 2, qc = lane & 3;
    int n = (np * 2 + sub) * 8 + qr;
    int k = kb * 16 + wi * 8 + 2 * qc;
    int col = (n >> 5) * 512 + cb * 32 + (n & 31);
    const float* U = dir ? U_b : U_f;
    float lo = U[(size_t)k * G4 + col];
    float hi = U[(size_t)(k + 1) * G4 + col];
    half2 h2 = __floats2half2_rn(lo, hi);
    g_Upk[widx] = *(uint32_t*)&h2;
}

// ---------------- pack [W_f|W_b] into same fragment order ------------------
__global__ __launch_bounds__(256) void prep_W(
    const float* __restrict__ W_f, const float* __restrict__ W_b)
{
    int widx  = blockIdx.x * 256 + threadIdx.x;   // < 2^20
    int word  = widx & 32767;
    int nb    = widx >> 15;
    int kb   = word >> 10;
    int np   = (word >> 7) & 7;
    int lane = (word >> 2) & 31;
    int q    = word & 3;
    int sub = q >> 1, wi = q & 1;
    int qr = lane >> 2, qc = lane & 3;
    int nl = (np * 2 + sub) * 8 + qr;
    int k  = kb * 16 + wi * 8 + 2 * qc;
    int c  = nb * 128 + nl;
    const float* W = (c < G4) ? (W_f + c) : (W_b + c - G4);
    float lo = W[(size_t)k * G4];
    float hi = W[(size_t)(k + 1) * G4];
    half2 h2 = __floats2half2_rn(lo, hi);
    g_Wpk[widx] = *(uint32_t*)&h2;
}

// ---------------- MMA helpers ----------------------------------------------
#define MMA16816(d, a, b0v, b1v)                                              \
    asm volatile(                                                             \
        "mma.sync.aligned.m16n8k16.row.col.f32.f16.f16.f32 "                  \
        "{%0,%1,%2,%3},{%4,%5,%6,%7},{%8,%9},{%0,%1,%2,%3};"                  \
        : "+f"(d[0]), "+f"(d[1]), "+f"(d[2]), "+f"(d[3])                      \
        : "r"(a[0]), "r"(a[1]), "r"(a[2]), "r"(a[3]), "r"(b0v), "r"(b1v))

#define LDSM4(r, addr)                                                        \
    asm volatile("ldmatrix.sync.aligned.m8n8.x4.shared.b16 "                  \
                 "{%0,%1,%2,%3}, [%4];"                                       \
                 : "=r"(r[0]), "=r"(r[1]), "=r"(r[2]), "=r"(r[3])             \
                 : "r"(addr))

extern __shared__ char smem_dyn[];

// ---------------- Phase 1: fused gather + fp16 tensor-core GEMM ------------
#define ESTR 520   // A staging row stride in halves (padded layout)

__global__ __launch_bounds__(256, 1) void embed_mma(
    const int* __restrict__ x, const float* __restrict__ emb,
    const float* __restrict__ b_f, const float* __restrict__ b_b)
{
    __shared__ int ids_s[128];
    __half* hA = (__half*)smem_dyn;                // 128 x ESTR halves

    const int tid  = threadIdx.x;
    const int lane = tid & 31;
    const int wid  = tid >> 5;
    const int wm   = wid >> 1;          // 0..3 : 32 rows
    const int wn   = wid & 1;           // 0..1 : 128 cols
    const int qr = lane >> 2, qc = lane & 3;
    const int mBase = blockIdx.y * 128;
    const int nb    = blockIdx.x * 2 + wn;

    if (tid < 128) ids_s[tid] = x[mBase + tid];
    __syncthreads();

    // Stage full A tile: 128 rows x 512 k, fp32 -> fp16
    {
        int row = tid >> 1, seg = tid & 1;
        const float* src = emb + (size_t)ids_s[row] * EMBED + seg * 256;
        __half* d = hA + row * ESTR + seg * 256;
        #pragma unroll
        for (int i = 0; i < 64; i++) {
            float4 v = *(const float4*)(src + i * 4);
            *(half2*)(d + i * 4)     = __floats2half2_rn(v.x, v.y);
            *(half2*)(d + i * 4 + 2) = __floats2half2_rn(v.z, v.w);
        }
    }
    __syncthreads();

    int lm_row = (lane & 7) + ((lane >> 3) & 1) * 8;
    int lm_kh  = (lane >> 4) * 8;
    uint32_t hA_s = (uint32_t)__cvta_generic_to_shared(hA);
    uint32_t lmaddr0 = hA_s + (uint32_t)(((wm * 32 + 0  + lm_row) * ESTR + lm_kh) * 2);
    uint32_t lmaddr1 = hA_s + (uint32_t)(((wm * 32 + 16 + lm_row) * ESTR + lm_kh) * 2);

    const uint32_t* gW = g_Wpk + (size_t)nb * 32768;

    float acc[2][16][4];
    #pragma unroll
    for (int mt = 0; mt < 2; mt++)
        #pragma unroll
        for (int j = 0; j < 16; j++)
            #pragma unroll
            for (int r = 0; r < 4; r++) acc[mt][j][r] = 0.f;

    #pragma unroll 2
    for (int kb = 0; kb < 32; kb++) {
        uint32_t a0[4], a1[4];
        LDSM4(a0, lmaddr0 + kb * 32);
        LDSM4(a1, lmaddr1 + kb * 32);
        uint4 Bv[8];
        #pragma unroll
        for (int np = 0; np < 8; np++)
            Bv[np] = *(const uint4*)&gW[(((kb * 8 + np) * 32 + lane) << 2)];
        #pragma unroll
        for (int j = 0; j < 16; j++) {
            uint32_t b0 = (j & 1) ? Bv[j >> 1].z : Bv[j >> 1].x;
            uint32_t b1 = (j & 1) ? Bv[j >> 1].w : Bv[j >> 1].y;
            MMA16816(acc[0][j], a0, b0, b1);
            MMA16816(acc[1][j], a1, b0, b1);
        }
    }

    // Epilogue: add bias, store fp16 z to g_xW
    const float* bp = (nb < 16) ? (b_f + nb * 128) : (b_b + nb * 128 - G4);
    #pragma unroll
    for (int mt = 0; mt < 2; mt++) {
        #pragma unroll
        for (int j = 0; j < 16; j++) {
            int row = mBase + wm * 32 + mt * 16 + qr;
            int cl  = j * 8 + qc * 2;
            float bx = bp[cl], by = bp[cl + 1];
            half2 lo = __floats2half2_rn(acc[mt][j][0] + bx, acc[mt][j][1] + by);
            half2 hi = __floats2half2_rn(acc[mt][j][2] + bx, acc[mt][j][3] + by);
            *(half2*)&g_xW[(size_t)row * NZ + nb * 128 + cl]       = lo;
            *(half2*)&g_xW[(size_t)(row + 8) * NZ + nb * 128 + cl] = hi;
        }
    }
}

// ---------------- Phase 2: persistent bidirectional LSTM -------------------
// 128 CTAs x 256 thr. CTA (dir, cb, rb): 64 rows x 128 zcols (4 gates x 32 h).
// U fp16 resident in SMEM; c + own h slice resident in REGISTERS; h exchanged
// via fp16 global double buffer; A staged with XOR swizzle (no padding).
#define ZSTR 132   // z exchange row stride in floats

__global__ __launch_bounds__(256, 1) void lstm_persist(
    const int* __restrict__ x, float* __restrict__ out)
{
    uint32_t* uB  = (uint32_t*)smem_dyn;           // 128 KB
    char*     hAb = smem_dyn + 131072;             // 64 KB swizzled A staging
    float*    shZ = (float*)(smem_dyn + 131072);   // alias (post-sync)

    const int tid  = threadIdx.x;
    const int lane = tid & 31;
    const int wid  = tid >> 5;
    const int bid  = blockIdx.x;
    const int dir  = bid >> 6;
    const int cb   = (bid >> 2) & 15;
    const int rb   = bid & 3;
    const int rBase  = rb * 64;
    const int cbBase = cb * 32;

    // Load U slice once (resident for all steps)
    {
        const uint4* src = (const uint4*)(g_Upk + (size_t)(dir * 16 + cb) * 32768);
        uint4* dst = (uint4*)uB;
        #pragma unroll
        for (int i = 0; i < 32; i++) dst[i * 256 + tid] = src[i * 256 + tid];
    }

    // Register-resident state for this thread's 8 (row, col) cells
    float creg[8], hreg[8];
    #pragma unroll
    for (int e = 0; e < 8; e++) { creg[e] = 0.f; hreg[e] = 0.f; }
    // Zero h16[0] slice (this CTA's ownership)
    #pragma unroll
    for (int e = 0; e < 8; e++) {
        int row = e * 8 + wid;
        g_h16[0][dir][(rBase + row) * UNITS + cbBase + lane] = __float2half(0.f);
    }

    const int wm = wid >> 2;
    const int wn = wid & 3;
    const int qr = lane >> 2, qc = lane & 3;

    // ldmatrix swizzled base: addr(kb) = C0 ^ (kb*32), second frag +16KB
    const int lrow = wm * 32 + (lane & 7) + ((lane >> 3) & 1) * 8;   // a0 row
    const int hi   = lane >> 4;
    const int r7   = lrow & 7;
    uint32_t hA_s = (uint32_t)__cvta_generic_to_shared(hAb);
    const uint32_t C0 = hA_s + (uint32_t)(lrow * 1024 + ((hi ^ (r7 & 1)) * 16) + (r7 >> 1) * 32);

    // staging thread mapping
    const int srow = tid >> 2, ssub = tid & 3, sr7 = srow & 7;

    // ---- prefetch step 0 (xW + mask; independent of peer h) ----
    float xwp[8][4];
    bool  mreg[8];
    {
        int t = dir ? (T_ - 1) : 0;
        #pragma unroll
        for (int e = 0; e < 8; e++) {
            int s = rBase + e * 8 + wid;
            const __half* p = g_xW + ((size_t)s * T_ + t) * NZ + dir * G4 + cbBase + lane;
            #pragma unroll
            for (int g = 0; g < 4; g++) xwp[e][g] = __half2float(p[g * 512]);
            mreg[e] = (x[s * T_ + t] != 0);
        }
    }

    for (int sstep = 0; sstep < T_; sstep++) {
        grid_sync();
        const int parity = sstep & 1;
        const __half* h16cur = g_h16[parity][dir];
        __half*       h16nxt = g_h16[parity ^ 1][dir];

        // Stage h tile (64 rows x 512 halves) -> swizzled SMEM, pure copy
        {
            const __half* src = h16cur + (size_t)(rBase + srow) * UNITS;
            #pragma unroll
            for (int i = 0; i < 16; i++) {
                int u = i * 4 + ssub;
                uint4 v = *(const uint4*)(src + u * 8);
                *(uint4*)(hAb + srow * 1024 + ((u ^ sr7) * 16)) = v;
            }
        }
        __syncthreads();

        // K loop: z = h @ U (fp16 MMA, fp32 accum)
        float acc[2][4][4];
        #pragma unroll
        for (int mt = 0; mt < 2; mt++)
            #pragma unroll
            for (int nt = 0; nt < 4; nt++)
                #pragma unroll
                for (int r = 0; r < 4; r++) acc[mt][nt][r] = 0.f;

        #pragma unroll 4
        for (int kb = 0; kb < 32; kb++) {
            uint32_t a0[4], a1[4];
            uint32_t ad0 = C0 ^ (uint32_t)(kb << 5);
            LDSM4(a0, ad0);
            LDSM4(a1, ad0 + 16384);
            uint4 B0 = *(const uint4*)&uB[((kb * 8 + wn * 2    ) * 32 + lane) * 4];
            uint4 B1 = *(const uint4*)&uB[((kb * 8 + wn * 2 + 1) * 32 + lane) * 4];
            MMA16816(acc[0][0], a0, B0.x, B0.y);
            MMA16816(acc[0][1], a0, B0.z, B0.w);
            MMA16816(acc[0][2], a0, B1.x, B1.y);
            MMA16816(acc[0][3], a0, B1.z, B1.w);
            MMA16816(acc[1][0], a1, B0.x, B0.y);
            MMA16816(acc[1][1], a1, B0.z, B0.w);
            MMA16816(acc[1][2], a1, B1.x, B1.y);
            MMA16816(acc[1][3], a1, B1.z, B1.w);
        }
        __syncthreads();   // done reading hAb; reuse region for z

        #pragma unroll
        for (int mt = 0; mt < 2; mt++)
            #pragma unroll
            for (int nt = 0; nt < 4; nt++) {
                int row0 = wm * 32 + mt * 16 + qr;
                int col  = wn * 32 + nt * 8 + qc * 2;
                *(float2*)&shZ[row0 * ZSTR + col] =
                    make_float2(acc[mt][nt][0], acc[mt][nt][1]);
                *(float2*)&shZ[(row0 + 8) * ZSTR + col] =
                    make_float2(acc[mt][nt][2], acc[mt][nt][3]);
            }
        __syncthreads();

        // Fused gate epilogue; state in registers; write h fp16 for peers
        #pragma unroll
        for (int e = 0; e < 8; e++) {
            int row = e * 8 + wid;
            int hl  = lane;
            float zi = shZ[row * ZSTR +       hl] + xwp[e][0];
            float zf = shZ[row * ZSTR +  32 + hl] + xwp[e][1];
            float zg = shZ[row * ZSTR +  64 + hl] + xwp[e][2];
            float zo = shZ[row * ZSTR +  96 + hl] + xwp[e][3];
            float ig = sigm(zi), fg = sigm(zf);
            float gg = tanhf(zg), og = sigm(zo);
            float cnew = fg * creg[e] + ig * gg;
            float hnew = og * tanhf(cnew);
            if (mreg[e]) { creg[e] = cnew; hreg[e] = hnew; }
            h16nxt[(rBase + row) * UNITS + cbBase + lane] = __float2half(hreg[e]);
        }

        // Prefetch next step's xW + mask (pre-barrier, hides DRAM latency)
        if (sstep + 1 < T_) {
            int t = dir ? (T_ - 2 - sstep) : (sstep + 1);
            #pragma unroll
            for (int e = 0; e < 8; e++) {
                int s = rBase + e * 8 + wid;
                const __half* p = g_xW + ((size_t)s * T_ + t) * NZ + dir * G4 + cbBase + lane;
                #pragma unroll
                for (int g = 0; g < 4; g++) xwp[e][g] = __half2float(p[g * 512]);
                mreg[e] = (x[s * T_ + t] != 0);
            }
        }
    }

    // Output straight from registers: out[s][dir*512 + hcol]
    #pragma unroll
    for (int e = 0; e < 8; e++) {
        int s = rBase + e * 8 + wid;
        out[s * 1024 + dir * 512 + cbBase + lane] = hreg[e];
    }
}

// ---------------- launcher -------------------------------------------------
extern "C" void kernel_launch(void* const* d_in, const int* in_sizes, int n_in,
                              void* d_out, int out_size)
{
    const int*   x   = (const int*)  d_in[0];
    const float* emb = (const float*)d_in[1];
    const float* W_f = (const float*)d_in[2];
    const float* U_f = (const float*)d_in[3];
    const float* b_f = (const float*)d_in[4];
    const float* W_b = (const float*)d_in[5];
    const float* U_b = (const float*)d_in[6];
    const float* b_b = (const float*)d_in[7];
    float* out = (float*)d_out;

    cudaFuncSetAttribute(embed_mma,
                         cudaFuncAttributeMaxDynamicSharedMemorySize, 133120);
    cudaFuncSetAttribute(lstm_persist,
                         cudaFuncAttributeMaxDynamicSharedMemorySize, 196608);

    prep_U<<<(2 * 16 * 32768) / 256, 256>>>(U_f, U_b);
    prep_W<<<(32 * 32768) / 256, 256>>>(W_f, W_b);
    embed_mma<<<dim3(16, 256), 256, 133120>>>(x, emb, b_f, b_b);
    lstm_persist<<<NCTA, 256, 196608>>>(x, out);
}

// round 7
// speedup vs baseline: 5.7549x; 1.0155x over previous
#include <cuda_runtime.h>
#include <cuda_fp16.h>
#include <math.h>
#include <stdint.h>

// Problem constants
#define T_     128
#define NSEQ   256          // B*S
#define EMBED  512
#define UNITS  512
#define G4     2048         // 4*UNITS
#define NZ     4096         // both directions
#define NCTA   128
#define GSZ    16           // CTAs per dependency group (dir, rb)

// ---------------- scratch (device globals) ---------------------------------
__device__ __half   g_xW[(size_t)NSEQ * T_ * NZ];  // fp16 [s*T+t][4096] fwd|bwd, bias incl
__device__ __half   g_h16[2][2][NSEQ * UNITS];     // fp16 h, [parity][dir]
__device__ uint32_t g_Upk[2 * 16 * 32768];         // fp16 frag-packed U per (dir,cb) slice
__device__ uint32_t g_Wpk[32 * 32768];             // fp16 frag-packed [W_f|W_b] per 128-col slice

struct alignas(128) Bar { unsigned cnt; unsigned gen; };
__device__ Bar g_bars[8];                          // one per (dir, rb) group

__device__ __forceinline__ float sigm(float x) { return 1.f / (1.f + expf(-x)); }

// ---------------- 16-CTA group barrier -------------------------------------
__device__ __forceinline__ void group_sync(int gid) {
    __syncthreads();
    if (threadIdx.x == 0) {
        __threadfence();
        volatile unsigned* genp = &g_bars[gid].gen;
        unsigned gen = *genp;
        if (atomicAdd(&g_bars[gid].cnt, 1u) == GSZ - 1) {
            g_bars[gid].cnt = 0;
            __threadfence();
            *genp = gen + 1;
        } else {
            while (*genp == gen) { __nanosleep(20); }
            __threadfence();
        }
    }
    __syncthreads();
}

// ---------------- pack U into fp16 MMA-fragment order ----------------------
__global__ __launch_bounds__(256) void prep_U(
    const float* __restrict__ U_f, const float* __restrict__ U_b)
{
    int widx  = blockIdx.x * 256 + threadIdx.x;   // < 2^20
    int word  = widx & 32767;
    int slice = widx >> 15;
    int dir = slice >> 4, cb = slice & 15;
    int kb   = word >> 10;
    int np   = (word >> 7) & 7;
    int lane = (word >> 2) & 31;
    int q    = word & 3;
    int sub = q >> 1, wi = q & 1;
    int qr = lane >> 2, qc = lane & 3;
    int n = (np * 2 + sub) * 8 + qr;
    int k = kb * 16 + wi * 8 + 2 * qc;
    int col = (n >> 5) * 512 + cb * 32 + (n & 31);
    const float* U = dir ? U_b : U_f;
    float lo = U[(size_t)k * G4 + col];
    float hi = U[(size_t)(k + 1) * G4 + col];
    half2 h2 = __floats2half2_rn(lo, hi);
    g_Upk[widx] = *(uint32_t*)&h2;
}

// ---------------- pack [W_f|W_b] into same fragment order ------------------
__global__ __launch_bounds__(256) void prep_W(
    const float* __restrict__ W_f, const float* __restrict__ W_b)
{
    int widx  = blockIdx.x * 256 + threadIdx.x;   // < 2^20
    int word  = widx & 32767;
    int nb    = widx >> 15;
    int kb   = word >> 10;
    int np   = (word >> 7) & 7;
    int lane = (word >> 2) & 31;
    int q    = word & 3;
    int sub = q >> 1, wi = q & 1;
    int qr = lane >> 2, qc = lane & 3;
    int nl = (np * 2 + sub) * 8 + qr;
    int k  = kb * 16 + wi * 8 + 2 * qc;
    int c  = nb * 128 + nl;
    const float* W = (c < G4) ? (W_f + c) : (W_b + c - G4);
    float lo = W[(size_t)k * G4];
    float hi = W[(size_t)(k + 1) * G4];
    half2 h2 = __floats2half2_rn(lo, hi);
    g_Wpk[widx] = *(uint32_t*)&h2;
}

// ---------------- MMA helpers ----------------------------------------------
#define MMA16816(d, a, b0v, b1v)                                              \
    asm volatile(                                                             \
        "mma.sync.aligned.m16n8k16.row.col.f32.f16.f16.f32 "                  \
        "{%0,%1,%2,%3},{%4,%5,%6,%7},{%8,%9},{%0,%1,%2,%3};"                  \
        : "+f"(d[0]), "+f"(d[1]), "+f"(d[2]), "+f"(d[3])                      \
        : "r"(a[0]), "r"(a[1]), "r"(a[2]), "r"(a[3]), "r"(b0v), "r"(b1v))

#define LDSM4(r, addr)                                                        \
    asm volatile("ldmatrix.sync.aligned.m8n8.x4.shared.b16 "                  \
                 "{%0,%1,%2,%3}, [%4];"                                       \
                 : "=r"(r[0]), "=r"(r[1]), "=r"(r[2]), "=r"(r[3])             \
                 : "r"(addr))

extern __shared__ char smem_dyn[];

// ---------------- Phase 1: fused gather + fp16 tensor-core GEMM ------------
#define ESTR 520   // A staging row stride in halves (padded layout)

__global__ __launch_bounds__(256, 1) void embed_mma(
    const int* __restrict__ x, const float* __restrict__ emb,
    const float* __restrict__ b_f, const float* __restrict__ b_b)
{
    __shared__ int ids_s[128];
    __half* hA = (__half*)smem_dyn;                // 128 x ESTR halves

    const int tid  = threadIdx.x;
    const int lane = tid & 31;
    const int wid  = tid >> 5;
    const int wm   = wid >> 1;          // 0..3 : 32 rows
    const int wn   = wid & 1;           // 0..1 : 128 cols
    const int qr = lane >> 2, qc = lane & 3;
    const int mBase = blockIdx.y * 128;
    const int nb    = blockIdx.x * 2 + wn;

    if (tid < 128) ids_s[tid] = x[mBase + tid];
    __syncthreads();

    // Stage full A tile: 128 rows x 512 k, fp32 -> fp16
    {
        int row = tid >> 1, seg = tid & 1;
        const float* src = emb + (size_t)ids_s[row] * EMBED + seg * 256;
        __half* d = hA + row * ESTR + seg * 256;
        #pragma unroll
        for (int i = 0; i < 64; i++) {
            float4 v = *(const float4*)(src + i * 4);
            *(half2*)(d + i * 4)     = __floats2half2_rn(v.x, v.y);
            *(half2*)(d + i * 4 + 2) = __floats2half2_rn(v.z, v.w);
        }
    }
    __syncthreads();

    int lm_row = (lane & 7) + ((lane >> 3) & 1) * 8;
    int lm_kh  = (lane >> 4) * 8;
    uint32_t hA_s = (uint32_t)__cvta_generic_to_shared(hA);
    uint32_t lmaddr0 = hA_s + (uint32_t)(((wm * 32 + 0  + lm_row) * ESTR + lm_kh) * 2);
    uint32_t lmaddr1 = hA_s + (uint32_t)(((wm * 32 + 16 + lm_row) * ESTR + lm_kh) * 2);

    const uint32_t* gW = g_Wpk + (size_t)nb * 32768;

    float acc[2][16][4];
    #pragma unroll
    for (int mt = 0; mt < 2; mt++)
        #pragma unroll
        for (int j = 0; j < 16; j++)
            #pragma unroll
            for (int r = 0; r < 4; r++) acc[mt][j][r] = 0.f;

    #pragma unroll 2
    for (int kb = 0; kb < 32; kb++) {
        uint32_t a0[4], a1[4];
        LDSM4(a0, lmaddr0 + kb * 32);
        LDSM4(a1, lmaddr1 + kb * 32);
        uint4 Bv[8];
        #pragma unroll
        for (int np = 0; np < 8; np++)
            Bv[np] = *(const uint4*)&gW[(((kb * 8 + np) * 32 + lane) << 2)];
        #pragma unroll
        for (int j = 0; j < 16; j++) {
            uint32_t b0 = (j & 1) ? Bv[j >> 1].z : Bv[j >> 1].x;
            uint32_t b1 = (j & 1) ? Bv[j >> 1].w : Bv[j >> 1].y;
            MMA16816(acc[0][j], a0, b0, b1);
            MMA16816(acc[1][j], a1, b0, b1);
        }
    }

    // Epilogue: add bias, store fp16 z to g_xW
    const float* bp = (nb < 16) ? (b_f + nb * 128) : (b_b + nb * 128 - G4);
    #pragma unroll
    for (int mt = 0; mt < 2; mt++) {
        #pragma unroll
        for (int j = 0; j < 16; j++) {
            int row = mBase + wm * 32 + mt * 16 + qr;
            int cl  = j * 8 + qc * 2;
            float bx = bp[cl], by = bp[cl + 1];
            half2 lo = __floats2half2_rn(acc[mt][j][0] + bx, acc[mt][j][1] + by);
            half2 hi = __floats2half2_rn(acc[mt][j][2] + bx, acc[mt][j][3] + by);
            *(half2*)&g_xW[(size_t)row * NZ + nb * 128 + cl]       = lo;
            *(half2*)&g_xW[(size_t)(row + 8) * NZ + nb * 128 + cl] = hi;
        }
    }
}

// ---------------- Phase 2: persistent bidirectional LSTM -------------------
// 128 CTAs x 512 thr (16 warps). CTA (dir, cb, rb): 64 rows x 128 zcols.
// Warp (wm 0..3, wn 0..3): 16 rows x 32 zcols (wn = gate). 16-CTA group sync.
#define ZSTR 132   // z exchange row stride in floats

__global__ __launch_bounds__(512, 1) void lstm_persist(
    const int* __restrict__ x, float* __restrict__ out)
{
    uint32_t* uB  = (uint32_t*)smem_dyn;           // 128 KB
    char*     hAb = smem_dyn + 131072;             // 64 KB swizzled A staging
    float*    shZ = (float*)(smem_dyn + 131072);   // alias (post-sync)

    const int tid  = threadIdx.x;
    const int lane = tid & 31;
    const int wid  = tid >> 5;                     // 0..15
    const int bid  = blockIdx.x;
    const int dir  = bid >> 6;
    const int cb   = (bid >> 2) & 15;
    const int rb   = bid & 3;
    const int gid  = dir * 4 + rb;
    const int rBase  = rb * 64;
    const int cbBase = cb * 32;

    // Load U slice once (resident for all steps)
    {
        const uint4* src = (const uint4*)(g_Upk + (size_t)(dir * 16 + cb) * 32768);
        uint4* dst = (uint4*)uB;
        #pragma unroll
        for (int i = 0; i < 16; i++) dst[i * 512 + tid] = src[i * 512 + tid];
    }

    // Register-resident state: 4 (row, col) cells per thread
    float creg[4], hreg[4];
    #pragma unroll
    for (int e = 0; e < 4; e++) { creg[e] = 0.f; hreg[e] = 0.f; }
    #pragma unroll
    for (int e = 0; e < 4; e++) {
        int row = e * 16 + wid;
        g_h16[0][dir][(rBase + row) * UNITS + cbBase + lane] = __float2half(0.f);
    }

    const int wm = wid >> 2;          // 0..3 : 16 rows
    const int wn = wid & 3;           // 0..3 : 32 zcols (gate)
    const int qr = lane >> 2, qc = lane & 3;

    // ldmatrix swizzled base: addr(kb) = C0 ^ (kb*32)
    const int lrow = wm * 16 + (lane & 7) + ((lane >> 3) & 1) * 8;
    const int hi   = lane >> 4;
    const int r7   = lrow & 7;
    uint32_t hA_s = (uint32_t)__cvta_generic_to_shared(hAb);
    const uint32_t C0 = hA_s + (uint32_t)(lrow * 1024 + ((hi ^ (r7 & 1)) * 16) + (r7 >> 1) * 32);

    // staging thread mapping: each thread copies 8 x 16B of one row
    const int srow = tid >> 3, ssub = tid & 7, sr7 = srow & 7;

    // ---- prefetch step 0 (xW + mask) ----
    float xwp[4][4];
    bool  mreg[4];
    {
        int t = dir ? (T_ - 1) : 0;
        #pragma unroll
        for (int e = 0; e < 4; e++) {
            int s = rBase + e * 16 + wid;
            const __half* p = g_xW + ((size_t)s * T_ + t) * NZ + dir * G4 + cbBase + lane;
            #pragma unroll
            for (int g = 0; g < 4; g++) xwp[e][g] = __half2float(p[g * 512]);
            mreg[e] = (x[s * T_ + t] != 0);
        }
    }

    for (int sstep = 0; sstep < T_; sstep++) {
        group_sync(gid);
        const int parity = sstep & 1;
        const __half* h16cur = g_h16[parity][dir];
        __half*       h16nxt = g_h16[parity ^ 1][dir];

        // Stage h tile (64 rows x 512 halves) -> swizzled SMEM
        {
            const __half* src = h16cur + (size_t)(rBase + srow) * UNITS;
            #pragma unroll
            for (int i = 0; i < 8; i++) {
                int u = i * 8 + ssub;
                uint4 v = *(const uint4*)(src + u * 8);
                *(uint4*)(hAb + srow * 1024 + ((u ^ sr7) * 16)) = v;
            }
        }
        __syncthreads();

        // K loop: z = h @ U (fp16 MMA, fp32 accum); warp tile 16x32
        float acc[4][4];
        #pragma unroll
        for (int nt = 0; nt < 4; nt++)
            #pragma unroll
            for (int r = 0; r < 4; r++) acc[nt][r] = 0.f;

        #pragma unroll 8
        for (int kb = 0; kb < 32; kb++) {
            uint32_t a0[4];
            LDSM4(a0, C0 ^ (uint32_t)(kb << 5));
            uint4 B0 = *(const uint4*)&uB[((kb * 8 + wn * 2    ) * 32 + lane) * 4];
            uint4 B1 = *(const uint4*)&uB[((kb * 8 + wn * 2 + 1) * 32 + lane) * 4];
            MMA16816(acc[0], a0, B0.x, B0.y);
            MMA16816(acc[1], a0, B0.z, B0.w);
            MMA16816(acc[2], a0, B1.x, B1.y);
            MMA16816(acc[3], a0, B1.z, B1.w);
        }
        __syncthreads();   // done reading hAb; reuse region for z

        #pragma unroll
        for (int nt = 0; nt < 4; nt++) {
            int row0 = wm * 16 + qr;
            int col  = wn * 32 + nt * 8 + qc * 2;
            *(float2*)&shZ[row0 * ZSTR + col] = make_float2(acc[nt][0], acc[nt][1]);
            *(float2*)&shZ[(row0 + 8) * ZSTR + col] = make_float2(acc[nt][2], acc[nt][3]);
        }
        __syncthreads();

        // Fused gate epilogue; state in registers; write h fp16 for peers
        #pragma unroll
        for (int e = 0; e < 4; e++) {
            int row = e * 16 + wid;
            int hl  = lane;
            float zi = shZ[row * ZSTR +       hl] + xwp[e][0];
            float zf = shZ[row * ZSTR +  32 + hl] + xwp[e][1];
            float zg = shZ[row * ZSTR +  64 + hl] + xwp[e][2];
            float zo = shZ[row * ZSTR +  96 + hl] + xwp[e][3];
            float ig = sigm(zi), fg = sigm(zf);
            float gg = tanhf(zg), og = sigm(zo);
            float cnew = fg * creg[e] + ig * gg;
            float hnew = og * tanhf(cnew);
            if (mreg[e]) { creg[e] = cnew; hreg[e] = hnew; }
            h16nxt[(rBase + row) * UNITS + cbBase + lane] = __float2half(hreg[e]);
        }

        // Prefetch next step's xW + mask (pre-barrier, hides DRAM latency)
        if (sstep + 1 < T_) {
            int t = dir ? (T_ - 2 - sstep) : (sstep + 1);
            #pragma unroll
            for (int e = 0; e < 4; e++) {
                int s = rBase + e * 16 + wid;
                const __half* p = g_xW + ((size_t)s * T_ + t) * NZ + dir * G4 + cbBase + lane;
                #pragma unroll
                for (int g = 0; g < 4; g++) xwp[e][g] = __half2float(p[g * 512]);
                mreg[e] = (x[s * T_ + t] != 0);
            }
        }
    }

    // Output straight from registers
    #pragma unroll
    for (int e = 0; e < 4; e++) {
        int s = rBase + e * 16 + wid;
        out[s * 1024 + dir * 512 + cbBase + lane] = hreg[e];
    }
}

// ---------------- launcher -------------------------------------------------
extern "C" void kernel_launch(void* const* d_in, const int* in_sizes, int n_in,
                              void* d_out, int out_size)
{
    const int*   x   = (const int*)  d_in[0];
    const float* emb = (const float*)d_in[1];
    const float* W_f = (const float*)d_in[2];
    const float* U_f = (const float*)d_in[3];
    const float* b_f = (const float*)d_in[4];
    const float* W_b = (const float*)d_in[5];
    const float* U_b = (const float*)d_in[6];
    const float* b_b = (const float*)d_in[7];
    float* out = (float*)d_out;

    cudaFuncSetAttribute(embed_mma,
                         cudaFuncAttributeMaxDynamicSharedMemorySize, 133120);
    cudaFuncSetAttribute(lstm_persist,
                         cudaFuncAttributeMaxDynamicSharedMemorySize, 196608);

    prep_U<<<(2 * 16 * 32768) / 256, 256>>>(U_f, U_b);
    prep_W<<<(32 * 32768) / 256, 256>>>(W_f, W_b);
    embed_mma<<<dim3(16, 256), 256, 133120>>>(x, emb, b_f, b_b);
    lstm_persist<<<NCTA, 512, 196608>>>(x, out);
}